// round 16
// baseline (speedup 1.0000x reference)
#include <cuda_runtime.h>
#include <cuda_fp16.h>
#include <cstdint>
#include <cstddef>
#include <math.h>

#define NROWS 131072
#define DIN   256
#define HID   1024
#define NEXP  100

// SMEM layout (halfs padded: 256 -> 264 per row, pitch 528 B, conflict-free ldmatrix)
#define ROWP      264
#define A_OFF     0
#define A_BYTES   (128 * ROWP * 2)           // 67584
#define B_OFF     A_BYTES                     // 67584
#define B_BYTES   (64 * ROWP * 2)            // 33792 per buffer; 4 buffers (2 per group)
#define B1_OFF    (B_OFF + 4 * B_BYTES)       // 202752
#define Y_OFF     (B1_OFF + HID * 4)          // 206848
#define SMEM_REQ  (Y_OFF + 4 * 128 * 4)       // 208896

// ---------------- static device scratch (no cudaMalloc allowed) ----------------
__device__ __align__(16) __half g_W1h[HID * DIN];    // fp16 W1 row-major [HID][DIN]
__device__ __align__(16) __half g_Wef16[NEXP * HID]; // fp16 We [E][HID]
__device__ int g_expert[NROWS];

// ---------------- PTX helpers (portable sm_80-class only; no tcgen05 on sm_103) ----
__device__ __forceinline__ uint32_t smem_to_u32(const void* p) {
    uint32_t a;
    asm("{ .reg .u64 t; cvta.to.shared.u64 t, %1; cvt.u32.u64 %0, t; }" : "=r"(a) : "l"(p));
    return a;
}
__device__ __forceinline__ void ldmatrix_x4(uint32_t& r0, uint32_t& r1, uint32_t& r2,
                                            uint32_t& r3, uint32_t addr) {
    asm volatile("ldmatrix.sync.aligned.m8n8.x4.shared.b16 {%0,%1,%2,%3}, [%4];"
                 : "=r"(r0), "=r"(r1), "=r"(r2), "=r"(r3) : "r"(addr));
}
__device__ __forceinline__ void mma_16816(float* c, const uint32_t* a, const uint32_t* b) {
    asm volatile(
        "mma.sync.aligned.m16n8k16.row.col.f32.f16.f16.f32 "
        "{%0,%1,%2,%3}, {%4,%5,%6,%7}, {%8,%9}, {%0,%1,%2,%3};"
        : "+f"(c[0]), "+f"(c[1]), "+f"(c[2]), "+f"(c[3])
        : "r"(a[0]), "r"(a[1]), "r"(a[2]), "r"(a[3]), "r"(b[0]), "r"(b[1]));
}
#define CP_ASYNC16(dst, src) \
    asm volatile("cp.async.cg.shared.global [%0], [%1], 16;" :: "r"(dst), "l"(src))
#define CP_COMMIT() asm volatile("cp.async.commit_group;")
#define CP_WAIT1()  asm volatile("cp.async.wait_group 1;")
#define CP_WAIT0()  asm volatile("cp.async.wait_group 0;")
#define BAR_GROUP(id) asm volatile("bar.sync %0, %1;" :: "r"(id), "r"(256) : "memory")

__device__ __forceinline__ uint32_t pack_h2(float lo, float hi) {
    uint32_t r;
    asm("cvt.rn.f16x2.f32 %0, %1, %2;" : "=r"(r) : "f"(hi), "f"(lo));
    return r;
}

// ---------------- merged prep kernel ----------------
__global__ void prep_all(const float* __restrict__ W1, const float* __restrict__ We,
                         const void* __restrict__ num, const void* __restrict__ c_in) {
    __shared__ int s_is64;
    if (threadIdx.x == 0) {
        // Index-width autodetect: int64 view of c yields values in [0,NEXP) for all
        // 50 words only if the buffer really is int64.
        const long long* cl = (const long long*)c_in;
        int ok = 1;
        for (int i = 0; i < 50; i++) {
            long long v = cl[i];
            if (v < 0 || v >= NEXP) { ok = 0; break; }
        }
        s_is64 = ok;
    }
    __syncthreads();
    int t = blockIdx.x * 256 + threadIdx.x;
    if (t < HID * DIN) g_W1h[t] = __float2half_rn(W1[t]);
    if (t < NEXP * HID) g_Wef16[t] = __float2half_rn(We[t]);
    if (t < NROWS) {
        int ev;
        if (s_is64) {
            int nv = (int)((const long long*)num)[t];
            ev = (int)((const long long*)c_in)[nv];
        } else {
            int nv = ((const int*)num)[t];
            ev = ((const int*)c_in)[nv];
        }
        g_expert[t] = ev;
    }
}

// ---------------- main fused kernel ----------------
// B chunk (64 hid-rows x 512 B) loaded by ONE group (256 threads) -> padded smem rows
__device__ __forceinline__ void issue_b(uint32_t sbase, int buf, int chunk, int gtid) {
#pragma unroll
    for (int it = 0; it < 8; it++) {
        int idx = gtid + 256 * it;           // 0..2047
        int row = idx >> 5, seg = idx & 31;
        const __half* src = g_W1h + (size_t)(chunk * 64 + row) * DIN + seg * 8;
        uint32_t dst = sbase + B_OFF + buf * B_BYTES + row * (ROWP * 2) + seg * 16;
        CP_ASYNC16(dst, src);
    }
}

__global__ void __launch_bounds__(512, 1) cmv_main(
    const float* __restrict__ x, const float* __restrict__ b1,
    const float* __restrict__ be, float* __restrict__ out)
{
    extern __shared__ char smem[];
    uint32_t sbase = smem_to_u32(smem);
    float* s_b1 = (float*)(smem + B1_OFF);
    float* s_y  = (float*)(smem + Y_OFF);    // [4 slots][128 rows]

    const int tid  = threadIdx.x;
    const int lane = tid & 31;
    const int wid  = tid >> 5;
    const int g    = wid >> 3;               // group 0: warps 0-7, group 1: warps 8-15
    const int wg   = wid & 7;                // warp-in-group: 4m x 2n of 32x32 tiles
    const int gtid = tid & 255;
    const int m_base = 32 * (wg >> 1);
    const int n_base = 32 * (wg & 1);
    const int row0_g = blockIdx.x * 128;

    // ---- 2-deep B prefetch per group, then stage A (fp32->fp16) + b1 ----
    // group g processes chunks g, g+2, g+4, ... (16 chunks of 64 cols);
    // buffer for iteration ci is g*2 + (ci & 1).
    issue_b(sbase, g * 2,     g,     gtid);  CP_COMMIT();
    issue_b(sbase, g * 2 + 1, g + 2, gtid);  CP_COMMIT();

    {
        const float4* xg = (const float4*)(x + (size_t)row0_g * DIN);
#pragma unroll
        for (int it = 0; it < 16; it++) {
            int idx = tid + 512 * it;        // 128 rows x 64 float4
            int row = idx >> 6, c4 = idx & 63;
            float4 v = xg[row * 64 + c4];
            uint2 h;
            h.x = pack_h2(v.x, v.y);
            h.y = pack_h2(v.z, v.w);
            *(uint2*)(smem + A_OFF + row * (ROWP * 2) + c4 * 8) = h;
        }
    }
    for (int i = tid; i < HID; i += 512) s_b1[i] = b1[i];
    __syncthreads();

    // per-thread expert rows (4 rows: m_base + 16i + 8h + lane/4)
    int er[4];
#pragma unroll
    for (int i = 0; i < 2; i++)
#pragma unroll
        for (int h = 0; h < 2; h++)
            er[2 * i + h] = g_expert[row0_g + m_base + 16 * i + 8 * h + (lane >> 2)];

    // ldmatrix base addresses (layout validated in R3)
    uint32_t a_addr0 = sbase + A_OFF +
        (uint32_t)((m_base + (lane & 15)) * (ROWP * 2) + ((lane >> 4) << 4));
    uint32_t b_addr0_rel = (uint32_t)((n_base + (lane & 7) + ((lane >> 4) << 3)) * (ROWP * 2)
                                      + (((lane >> 3) & 1) << 4));

    float yacc[4] = {0.f, 0.f, 0.f, 0.f};
    const int bar_id = 1 + g;

    for (int ci = 0; ci < 8; ci++) {
        const int c   = 2 * ci + g;          // group 0: even chunks, group 1: odd
        const int buf = g * 2 + (ci & 1);

        // deep pipeline: at most 1 outstanding group may remain (the NEXT chunk);
        // final iteration has no future load in flight -> wait for everything.
        if (ci == 7) { CP_WAIT0(); } else { CP_WAIT1(); }
        BAR_GROUP(bar_id);                   // whole group's B tile visible

        float C[2][4][4] = {};               // 32x32 warp tile, fp32 accum (32 regs)
        const uint32_t b_addr = sbase + B_OFF + buf * B_BYTES + b_addr0_rel;

#pragma unroll
        for (int k = 0; k < 16; k++) {
            uint32_t a[2][4];
#pragma unroll
            for (int i = 0; i < 2; i++)
                ldmatrix_x4(a[i][0], a[i][1], a[i][2], a[i][3],
                            a_addr0 + i * 16 * (ROWP * 2) + k * 32);
#pragma unroll
            for (int jj = 0; jj < 2; jj++) {
                uint32_t b[4];
                ldmatrix_x4(b[0], b[1], b[2], b[3],
                            b_addr + jj * 16 * (ROWP * 2) + k * 32);
#pragma unroll
                for (int i = 0; i < 2; i++) {
                    mma_16816(C[i][2 * jj],     a[i], b);
                    mma_16816(C[i][2 * jj + 1], a[i], b + 2);
                }
            }
        }

        BAR_GROUP(bar_id);                   // group done reading this buffer

        // refill the buffer just released (used again at ci+2) — has a full
        // MMA+epilogue window (~8k cyc) to land before its CP_WAIT
        if (ci < 6) { issue_b(sbase, buf, c + 4, gtid); CP_COMMIT(); }

        // ---- fused epilogue: y += relu(C + b1) . We[e] ----
        const int colb = c * 64 + n_base;
        const float2* bp = (const float2*)(s_b1 + colb);
#pragma unroll
        for (int i = 0; i < 2; i++) {
#pragma unroll
            for (int h = 0; h < 2; h++) {
                const uint32_t* wp =
                    (const uint32_t*)(g_Wef16 + (size_t)er[2 * i + h] * HID + colb);
                float acc = 0.f;
#pragma unroll
                for (int j = 0; j < 4; j++) {
                    float2 w = __half22float2(*(const __half2*)&wp[j * 4 + (lane & 3)]);
                    float2 bb = bp[j * 4 + (lane & 3)];
                    float h0 = fmaxf(C[i][j][2 * h]     + bb.x, 0.f);
                    float h1 = fmaxf(C[i][j][2 * h + 1] + bb.y, 0.f);
                    acc += h0 * w.x + h1 * w.y;
                }
                yacc[2 * i + h] += acc;
            }
        }
    }

    // quad reduce (lanes in a quad hold different cols of the same rows)
#pragma unroll
    for (int q = 0; q < 4; q++) {
        yacc[q] += __shfl_xor_sync(0xFFFFFFFFu, yacc[q], 1);
        yacc[q] += __shfl_xor_sync(0xFFFFFFFFu, yacc[q], 2);
    }
    if ((lane & 3) == 0) {
        const int slot = g * 2 + (wg & 1);   // {group, n-half}
#pragma unroll
        for (int i = 0; i < 2; i++)
#pragma unroll
            for (int h = 0; h < 2; h++)
                s_y[slot * 128 + m_base + 16 * i + 8 * h + (lane >> 2)] = yacc[2 * i + h];
    }
    __syncthreads();

    if (tid < 128) {
        float yv = s_y[tid] + s_y[128 + tid] + s_y[256 + tid] + s_y[384 + tid];
        int e = g_expert[row0_g + tid];
        yv += be[e];
        out[row0_g + tid] = 1.0f / (1.0f + expf(-yv));
    }
}

// ---------------- launch ----------------
extern "C" void kernel_launch(void* const* d_in, const int* in_sizes, int n_in,
                              void* d_out, int out_size) {
    const float* x  = (const float*)d_in[0];
    const float* W1 = (const float*)d_in[1];
    const float* b1 = (const float*)d_in[2];
    const float* We = (const float*)d_in[3];
    const float* be = (const float*)d_in[4];
    const void*  num = d_in[5];
    const void*  cc  = d_in[6];
    (void)in_sizes; (void)n_in; (void)out_size;

    cudaFuncSetAttribute(cmv_main, cudaFuncAttributeMaxDynamicSharedMemorySize, SMEM_REQ);

    prep_all<<<1024, 256>>>(W1, We, num, cc);
    cmv_main<<<1024, 512, SMEM_REQ>>>(x, b1, be, (float*)d_out);
}

// round 17
// speedup vs baseline: 1.1370x; 1.1370x over previous
#include <cuda_runtime.h>
#include <cuda_fp16.h>
#include <cstdint>
#include <cstddef>
#include <math.h>

#define NROWS 131072
#define DIN   256
#define HID   1024
#define NEXP  100
#define NCTA  148
#define NRB   1024   // row-blocks of 128 rows

// SMEM layout (halfs padded: 256 -> 264 per row, pitch 528 B, conflict-free ldmatrix)
#define ROWP      264
#define A_OFF     0
#define A_BYTES   (128 * ROWP * 2)           // 67584
#define B_OFF     A_BYTES                     // 67584
#define B_BYTES   (64 * ROWP * 2)            // 33792 per buffer (64 hid-rows per chunk)
#define B1_OFF    (B_OFF + 2 * B_BYTES)       // 135168
#define Y_OFF     (B1_OFF + HID * 4)          // 139264
#define SMEM_REQ  (Y_OFF + 4 * 128 * 4)       // 141312

// ---------------- static device scratch (no cudaMalloc allowed) ----------------
__device__ __align__(16) __half g_W1h[HID * DIN];    // fp16 W1 row-major [HID][DIN]
__device__ __align__(16) __half g_Wef16[NEXP * HID]; // fp16 We [E][HID]
__device__ int g_expert[NROWS];

// ---------------- PTX helpers (portable sm_80-class only; no tcgen05 on sm_103) ----
__device__ __forceinline__ uint32_t smem_to_u32(const void* p) {
    uint32_t a;
    asm("{ .reg .u64 t; cvta.to.shared.u64 t, %1; cvt.u32.u64 %0, t; }" : "=r"(a) : "l"(p));
    return a;
}
__device__ __forceinline__ void ldmatrix_x4(uint32_t& r0, uint32_t& r1, uint32_t& r2,
                                            uint32_t& r3, uint32_t addr) {
    asm volatile("ldmatrix.sync.aligned.m8n8.x4.shared.b16 {%0,%1,%2,%3}, [%4];"
                 : "=r"(r0), "=r"(r1), "=r"(r2), "=r"(r3) : "r"(addr));
}
// fp16-accumulate MMA: D,C = 2 b32 regs (4 halfs); validated R8/R10/R11
__device__ __forceinline__ void mma_16816_h(uint32_t* c, const uint32_t* a, const uint32_t* b) {
    asm volatile(
        "mma.sync.aligned.m16n8k16.row.col.f16.f16.f16.f16 "
        "{%0,%1}, {%2,%3,%4,%5}, {%6,%7}, {%0,%1};"
        : "+r"(c[0]), "+r"(c[1])
        : "r"(a[0]), "r"(a[1]), "r"(a[2]), "r"(a[3]), "r"(b[0]), "r"(b[1]));
}
#define CP_ASYNC16(dst, src) \
    asm volatile("cp.async.cg.shared.global [%0], [%1], 16;" :: "r"(dst), "l"(src))
#define CP_COMMIT() asm volatile("cp.async.commit_group;")
#define CP_WAIT0()  asm volatile("cp.async.wait_group 0;")
#define BAR_GROUP(id) asm volatile("bar.sync %0, %1;" :: "r"(id), "r"(256) : "memory")

__device__ __forceinline__ uint32_t pack_h2(float lo, float hi) {
    uint32_t r;
    asm("cvt.rn.f16x2.f32 %0, %1, %2;" : "=r"(r) : "f"(hi), "f"(lo));
    return r;
}

// ---------------- merged prep kernel ----------------
__global__ void prep_all(const float* __restrict__ W1, const float* __restrict__ We,
                         const void* __restrict__ num, const void* __restrict__ c_in) {
    __shared__ int s_is64;
    if (threadIdx.x == 0) {
        // Index-width autodetect: int64 view of c yields values in [0,NEXP) for all
        // 50 words only if the buffer really is int64.
        const long long* cl = (const long long*)c_in;
        int ok = 1;
        for (int i = 0; i < 50; i++) {
            long long v = cl[i];
            if (v < 0 || v >= NEXP) { ok = 0; break; }
        }
        s_is64 = ok;
    }
    __syncthreads();
    int t = blockIdx.x * 256 + threadIdx.x;
    if (t < HID * DIN) g_W1h[t] = __float2half_rn(W1[t]);
    if (t < NEXP * HID) g_Wef16[t] = __float2half_rn(We[t]);
    if (t < NROWS) {
        int ev;
        if (s_is64) {
            int nv = (int)((const long long*)num)[t];
            ev = (int)((const long long*)c_in)[nv];
        } else {
            int nv = ((const int*)num)[t];
            ev = ((const int*)c_in)[nv];
        }
        g_expert[t] = ev;
    }
}

// ---------------- main fused persistent kernel ----------------
// B chunk (64 hid-rows x 512 B) loaded by ONE group (256 threads) -> padded smem rows
__device__ __forceinline__ void issue_b(uint32_t sbase, int buf, int chunk, int gtid) {
#pragma unroll
    for (int it = 0; it < 8; it++) {
        int idx = gtid + 256 * it;           // 0..2047
        int row = idx >> 5, seg = idx & 31;
        const __half* src = g_W1h + (size_t)(chunk * 64 + row) * DIN + seg * 8;
        uint32_t dst = sbase + B_OFF + buf * B_BYTES + row * (ROWP * 2) + seg * 16;
        CP_ASYNC16(dst, src);
    }
}

__global__ void __launch_bounds__(512, 1) cmv_main(
    const float* __restrict__ x, const float* __restrict__ b1,
    const float* __restrict__ be, float* __restrict__ out)
{
    extern __shared__ char smem[];
    uint32_t sbase = smem_to_u32(smem);
    float* s_b1 = (float*)(smem + B1_OFF);
    float* s_y  = (float*)(smem + Y_OFF);    // [4 slots][128 rows]

    const int tid  = threadIdx.x;
    const int lane = tid & 31;
    const int wid  = tid >> 5;
    const int g    = wid >> 3;               // group 0: warps 0-7, group 1: warps 8-15
    const int wg   = wid & 7;                // warp-in-group: 4m x 2n of 32x32 tiles
    const int gtid = tid & 255;
    const int m_base = 32 * (wg >> 1);
    const int n_base = 32 * (wg & 1);
    const int bar_id = 1 + g;

    // b1 loaded ONCE for the whole persistent run
    for (int i = tid; i < HID; i += 512) s_b1[i] = b1[i];

    // ldmatrix base addresses (layout validated in R3)
    const uint32_t a_addr0 = sbase + A_OFF +
        (uint32_t)((m_base + (lane & 15)) * (ROWP * 2) + ((lane >> 4) << 4));
    const uint32_t b_addr0_rel = (uint32_t)((n_base + (lane & 7) + ((lane >> 4) << 3)) * (ROWP * 2)
                                            + (((lane >> 3) & 1) << 4));
    const uint32_t b_addr = sbase + B_OFF + g * B_BYTES + b_addr0_rel;

    for (int rb = blockIdx.x; rb < NRB; rb += NCTA) {
        const int row0_g = rb * 128;

        // ---- first B tile per group in flight ASAP, then stage A (fp32->fp16) ----
        issue_b(sbase, g, g, gtid);          // group g loads chunk g into buffer g
        CP_COMMIT();

        {
            const float4* xg = (const float4*)(x + (size_t)row0_g * DIN);
#pragma unroll
            for (int it = 0; it < 16; it++) {
                int idx = tid + 512 * it;    // 128 rows x 64 float4
                int row = idx >> 6, c4 = idx & 63;
                float4 v = xg[row * 64 + c4];
                uint2 h;
                h.x = pack_h2(v.x, v.y);
                h.y = pack_h2(v.z, v.w);
                *(uint2*)(smem + A_OFF + row * (ROWP * 2) + c4 * 8) = h;
            }
        }
        __syncthreads();

        // per-thread expert rows (4 rows: m_base + 16i + 8h + lane/4)
        int er[4];
#pragma unroll
        for (int i = 0; i < 2; i++)
#pragma unroll
            for (int h = 0; h < 2; h++)
                er[2 * i + h] = g_expert[row0_g + m_base + 16 * i + 8 * h + (lane >> 2)];

        float yacc[4] = {0.f, 0.f, 0.f, 0.f};

        for (int ci = 0; ci < 8; ci++) {
            const int c = 2 * ci + g;        // group 0: even chunks, group 1: odd

            CP_WAIT0();
            BAR_GROUP(bar_id);               // whole group's B tile visible

            // fp16 accumulators: 32x32 warp tile = 2 mtiles x 4 ntiles x 2 regs
            uint32_t Ch[2][4][2] = {};

#pragma unroll
            for (int k = 0; k < 16; k++) {
                uint32_t a[2][4];
#pragma unroll
                for (int i = 0; i < 2; i++)
                    ldmatrix_x4(a[i][0], a[i][1], a[i][2], a[i][3],
                                a_addr0 + i * 16 * (ROWP * 2) + k * 32);
#pragma unroll
                for (int jj = 0; jj < 2; jj++) {
                    uint32_t b[4];
                    ldmatrix_x4(b[0], b[1], b[2], b[3],
                                b_addr + jj * 16 * (ROWP * 2) + k * 32);
#pragma unroll
                    for (int i = 0; i < 2; i++) {
                        mma_16816_h(Ch[i][2 * jj],     a[i], b);
                        mma_16816_h(Ch[i][2 * jj + 1], a[i], b + 2);
                    }
                }
            }

            BAR_GROUP(bar_id);               // group done reading B buffer

            // prefetch next chunk NOW — hides behind epilogue + other warps' MMA
            if (ci < 7) { issue_b(sbase, g, c + 2, gtid); CP_COMMIT(); }

            // ---- fused epilogue: y += relu(C + b1) . We[e] ----
            const int colb = c * 64 + n_base;
            const float2* bp = (const float2*)(s_b1 + colb);
#pragma unroll
            for (int i = 0; i < 2; i++) {
#pragma unroll
                for (int h = 0; h < 2; h++) {
                    const uint32_t* wp =
                        (const uint32_t*)(g_Wef16 + (size_t)er[2 * i + h] * HID + colb);
                    float acc = 0.f;
#pragma unroll
                    for (int j = 0; j < 4; j++) {
                        float2 cv = __half22float2(*(const __half2*)&Ch[i][j][h]);
                        float2 w  = __half22float2(*(const __half2*)&wp[j * 4 + (lane & 3)]);
                        float2 bb = bp[j * 4 + (lane & 3)];
                        float h0 = fmaxf(cv.x + bb.x, 0.f);
                        float h1 = fmaxf(cv.y + bb.y, 0.f);
                        acc += h0 * w.x + h1 * w.y;
                    }
                    yacc[2 * i + h] += acc;
                }
            }
        }

        // quad reduce (lanes in a quad hold different cols of the same rows)
#pragma unroll
        for (int q = 0; q < 4; q++) {
            yacc[q] += __shfl_xor_sync(0xFFFFFFFFu, yacc[q], 1);
            yacc[q] += __shfl_xor_sync(0xFFFFFFFFu, yacc[q], 2);
        }
        if ((lane & 3) == 0) {
            const int slot = g * 2 + (wg & 1);   // {group, n-half}
#pragma unroll
            for (int i = 0; i < 2; i++)
#pragma unroll
                for (int h = 0; h < 2; h++)
                    s_y[slot * 128 + m_base + 16 * i + 8 * h + (lane >> 2)] = yacc[2 * i + h];
        }
        __syncthreads();

        if (tid < 128) {
            float yv = s_y[tid] + s_y[128 + tid] + s_y[256 + tid] + s_y[384 + tid];
            int e = g_expert[row0_g + tid];
            yv += be[e];
            out[row0_g + tid] = 1.0f / (1.0f + expf(-yv));
        }
        __syncthreads();   // protect s_y and A buffer before next row-block restages
    }
}

// ---------------- launch ----------------
extern "C" void kernel_launch(void* const* d_in, const int* in_sizes, int n_in,
                              void* d_out, int out_size) {
    const float* x  = (const float*)d_in[0];
    const float* W1 = (const float*)d_in[1];
    const float* b1 = (const float*)d_in[2];
    const float* We = (const float*)d_in[3];
    const float* be = (const float*)d_in[4];
    const void*  num = d_in[5];
    const void*  cc  = d_in[6];
    (void)in_sizes; (void)n_in; (void)out_size;

    cudaFuncSetAttribute(cmv_main, cudaFuncAttributeMaxDynamicSharedMemorySize, SMEM_REQ);

    prep_all<<<1024, 256>>>(W1, We, num, cc);
    cmv_main<<<NCTA, 512, SMEM_REQ>>>(x, b1, be, (float*)d_out);
}